// round 6
// baseline (speedup 1.0000x reference)
#include <cuda_runtime.h>

// GCBFSafetyLayer — final kernel (measured-best configuration, R2/R4).
//
// Algebraic reduction: L_g_h = dh_dx @ g is identically zero. dh_dx's nonzero
// state columns (position jacobian, cols 0..1) meet only g's zero rows (0..1);
// g's I/MASS rows (2..3) meet dh_dx's zero columns (2..3). In project(),
// an = ||a||^2 = 0 fails the (an > 1e-6) gate for every constraint on every
// iteration, so u is never modified and safe_action == raw_action BIT-EXACT
// (rel_err = 0.0 on every round). Kernel = copy d_in[3] (B*N*P = 65536 f32
// = 16384 float4) to d_out.
//
// Config history: 128 CTAs x 128 threads, one float4/thread, plain LDG/STG,
// regs=16 is the measured optimum (ncu 4.13-4.32 us, harness 4.58-4.61 us).
// Variants tried and rejected: bounds-checked 64x256 (harness 6.43), 2
// loads/thread @ 64 CTAs (4.93), __stcs streaming stores (5.41 — the .cs
// evict hint costs on the harness's d_out re-read). Duration is the
// launch/graph-replay floor: T_ovh ~5000 cyc + one DRAM round trip; DRAM at
// 0.8% of peak by construction.

__global__ __launch_bounds__(128, 1)
void gcbf_copy_kernel(const float4* __restrict__ src, float4* __restrict__ dst) {
    int i = blockIdx.x * 128 + threadIdx.x;
    dst[i] = src[i];
}

extern "C" void kernel_launch(void* const* d_in, const int* in_sizes, int n_in,
                              void* d_out, int out_size) {
    // inputs: [0] positions, [1] velocities, [2] obstacles, [3] raw_action
    gcbf_copy_kernel<<<128, 128>>>((const float4*)d_in[3], (float4*)d_out);
}

// round 7
// speedup vs baseline: 1.0227x; 1.0227x over previous
#include <cuda_runtime.h>

// GCBFSafetyLayer — final kernel. HOLD: this exact source is the measured
// optimum; R6 proved harness variance ±0.6us on identical binaries
// (4.58 / 4.61 / 5.76 us for byte-identical code), while ncu kernel dur
// stayed 4.13-4.48us across ALL variants ever tried. Further tuning = noise.
//
// Algebraic reduction (verified rel_err = 0.0, 7/7 rounds):
//   L_g_h = dh_dx @ g == 0 identically — dh_dx's nonzero state columns
//   (position jacobian, cols 0..1) hit only g's zero rows (0..1); g's I/MASS
//   rows (2..3) hit dh_dx's zero columns (2..3). In project(),
//   an = ||a||^2 = 0 fails the (an > 1e-6) gate for every constraint, every
//   iteration -> u never changes -> safe_action == raw_action BIT-EXACT.
// Kernel = copy d_in[3] (B*N*P = 65536 f32 = 16384 float4) to d_out.
//
// Rejected variants: bounds-checked 64x256 (6.43us), 2 loads/thread @64 CTAs
// (4.93us), __stcs streaming stores (5.41us — .cs evict costs on harness's
// d_out re-read). Duration = launch/graph-replay floor: T_ovh ~5000 cyc +
// one DRAM round trip; DRAM at 0.8% of peak by construction.

__global__ __launch_bounds__(128, 1)
void gcbf_copy_kernel(const float4* __restrict__ src, float4* __restrict__ dst) {
    int i = blockIdx.x * 128 + threadIdx.x;
    dst[i] = src[i];
}

extern "C" void kernel_launch(void* const* d_in, const int* in_sizes, int n_in,
                              void* d_out, int out_size) {
    // inputs: [0] positions, [1] velocities, [2] obstacles, [3] raw_action
    gcbf_copy_kernel<<<128, 128>>>((const float4*)d_in[3], (float4*)d_out);
}

// round 8
// speedup vs baseline: 1.2500x; 1.2222x over previous
#include <cuda_runtime.h>

// GCBFSafetyLayer — copy-engine variant probe.
//
// Algebraic reduction (verified rel_err = 0.0, 8/8 rounds):
//   L_g_h = dh_dx @ g == 0 identically — dh_dx's nonzero state columns
//   (position jacobian, cols 0..1) hit only g's zero rows (0..1); g's I/MASS
//   rows (2..3) hit dh_dx's zero columns (2..3). In project(),
//   an = ||a||^2 = 0 fails the (an > 1e-6) gate for every constraint, every
//   iteration -> u never changes -> safe_action == raw_action BIT-EXACT.
// Work = copy d_in[3] (B*N*P = 65536 f32 = 256 KB) to d_out.
//
// The SM-kernel version is pinned at the launch floor (ncu 4.13-4.48us across
// ALL variants; T_ovh ~5000 cyc dominates, DRAM at 0.8%). The only untested
// structural lever is the NODE TYPE: a captured cudaMemcpyAsync D2D becomes a
// copy-engine graph node, bypassing the SM launch path entirely. Harness
// rules explicitly allow async D2D memcpy under capture.
//
// If this regresses (CE descriptor path heavier than SM launch on this
// harness), revert to the R2/R4 kernel:
//   gcbf_copy_kernel<<<128,128>>> one float4/thread.

extern "C" void kernel_launch(void* const* d_in, const int* in_sizes, int n_in,
                              void* d_out, int out_size) {
    // inputs: [0] positions, [1] velocities, [2] obstacles, [3] raw_action
    cudaMemcpyAsync(d_out, d_in[3], (size_t)in_sizes[3] * sizeof(float),
                    cudaMemcpyDeviceToDevice, 0);
}